// round 13
// baseline (speedup 1.0000x reference)
#include <cuda_runtime.h>
#include <cuda_bf16.h>
#include <cstdint>

// Problem constants (fixed by the reference setup_inputs)
#define B_  128
#define L_  2048
#define H_  768
#define H4_ 192          // H / 4 floats per float4
#define CHUNK_ROWS 128
#define NCHUNKS (L_ / CHUNK_ROWS)   // 16

// Scratch: per-(span,batch,chunk) partial sums + arrival counters.
// __device__ globals (zero-initialized at module load; counters self-reset
// after each use so graph replays stay deterministic). No allocation.
__device__ float4       g_part[2 * B_ * NCHUNKS * H4_];   // 12.6 MB
__device__ unsigned int g_cnt[2 * B_];

// Clamped inclusive span [start, end] for batch b, span s (0=head,1=tail).
// JAX x64 is disabled by default -> entity_positions arrives as int32.
__device__ __forceinline__ void span_bounds(const int* __restrict__ pos,
                                            int b, int s, int& start, int& end) {
    int p0 = pos[b * 4 + s * 2];
    int p1 = pos[b * 4 + s * 2 + 1];
    int st = p0 < 0 ? 0 : (p0 > (L_ - 1) ? (L_ - 1) : p0);
    int en = p1 > (L_ - 1) ? (L_ - 1) : p1;
    if (en < st) en = st;
    start = st;
    end   = en;
}

// Single kernel: one block per (L-chunk, batch, span). Streaming loop is the
// proven 8-wide batched LDG.128 shape. Single-chunk spans write the output
// directly; multi-chunk spans write partials to scratch and the LAST
// arriving block combines them. d_out is written exactly once per element,
// so no pre-zeroing kernel and no output atomics are needed.
__global__ void __launch_bounds__(H4_)
entity_accum_kernel(const float4* __restrict__ seq4,
                    const int* __restrict__ pos,
                    float4* __restrict__ out4) {
    const int c = blockIdx.x;
    const int b = blockIdx.y;
    const int s = blockIdx.z;

    int start, end;
    span_bounds(pos, b, s, start, end);

    const int lo = max(start, c * CHUNK_ROWS);
    const int hi = min(end,   c * CHUNK_ROWS + CHUNK_ROWS - 1);
    if (lo > hi) return;

    const int c0 = start >> 7;           // first intersecting chunk
    const int c1 = end   >> 7;           // last intersecting chunk
    const int nact = c1 - c0 + 1;
    const float inv = 1.0f / (float)(end - start + 1);

    const int t = threadIdx.x;  // 0..191
    const float4* base = seq4 + (size_t)b * L_ * H4_ + t;

    float4 acc = make_float4(0.f, 0.f, 0.f, 0.f);

    int r = lo;
    // 8-row batched main loop: 8 independent LDG.128 in flight per thread.
    for (; r + 7 <= hi; r += 8) {
        float4 v0 = __ldg(base + (size_t)(r + 0) * H4_);
        float4 v1 = __ldg(base + (size_t)(r + 1) * H4_);
        float4 v2 = __ldg(base + (size_t)(r + 2) * H4_);
        float4 v3 = __ldg(base + (size_t)(r + 3) * H4_);
        float4 v4 = __ldg(base + (size_t)(r + 4) * H4_);
        float4 v5 = __ldg(base + (size_t)(r + 5) * H4_);
        float4 v6 = __ldg(base + (size_t)(r + 6) * H4_);
        float4 v7 = __ldg(base + (size_t)(r + 7) * H4_);
        acc.x += ((v0.x + v1.x) + (v2.x + v3.x)) + ((v4.x + v5.x) + (v6.x + v7.x));
        acc.y += ((v0.y + v1.y) + (v2.y + v3.y)) + ((v4.y + v5.y) + (v6.y + v7.y));
        acc.z += ((v0.z + v1.z) + (v2.z + v3.z)) + ((v4.z + v5.z) + (v6.z + v7.z));
        acc.w += ((v0.w + v1.w) + (v2.w + v3.w)) + ((v4.w + v5.w) + (v6.w + v7.w));
    }
    for (; r + 3 <= hi; r += 4) {
        float4 v0 = __ldg(base + (size_t)(r + 0) * H4_);
        float4 v1 = __ldg(base + (size_t)(r + 1) * H4_);
        float4 v2 = __ldg(base + (size_t)(r + 2) * H4_);
        float4 v3 = __ldg(base + (size_t)(r + 3) * H4_);
        acc.x += (v0.x + v1.x) + (v2.x + v3.x);
        acc.y += (v0.y + v1.y) + (v2.y + v3.y);
        acc.z += (v0.z + v1.z) + (v2.z + v3.z);
        acc.w += (v0.w + v1.w) + (v2.w + v3.w);
    }
    for (; r <= hi; ++r) {
        float4 v = __ldg(base + (size_t)r * H4_);
        acc.x += v.x; acc.y += v.y; acc.z += v.z; acc.w += v.w;
    }

    const size_t oidx = ((size_t)s * B_ + b) * H4_ + t;

    if (nact == 1) {
        // Sole contributor: write final value directly (no scratch, no count).
        out4[oidx] = make_float4(acc.x * inv, acc.y * inv, acc.z * inv, acc.w * inv);
        return;
    }

    // Publish partial, then arrive. Last arriver combines and writes output.
    g_part[(((size_t)s * B_ + b) * NCHUNKS + c) * H4_ + t] = acc;
    __threadfence();

    __shared__ int s_last;
    __syncthreads();
    if (t == 0) {
        unsigned int old = atomicAdd(&g_cnt[s * B_ + b], 1u);
        s_last = (old == (unsigned int)(nact - 1)) ? 1 : 0;
    }
    __syncthreads();

    if (s_last) {
        __threadfence();  // acquire partials published by other blocks
        float4 sum = make_float4(0.f, 0.f, 0.f, 0.f);
        const float4* p = g_part + (((size_t)s * B_ + b) * NCHUNKS + c0) * H4_ + t;
        #pragma unroll 4
        for (int k = 0; k < nact; ++k) {
            float4 v = p[(size_t)k * H4_];
            sum.x += v.x; sum.y += v.y; sum.z += v.z; sum.w += v.w;
        }
        out4[oidx] = make_float4(sum.x * inv, sum.y * inv, sum.z * inv, sum.w * inv);
        if (t == 0) g_cnt[s * B_ + b] = 0;   // reset for next graph replay
    }
}

extern "C" void kernel_launch(void* const* d_in, const int* in_sizes, int n_in,
                              void* d_out, int out_size) {
    const float4* seq4 = (const float4*)d_in[0];   // [B, L, H] fp32
    const int*    pos  = (const int*)d_in[1];      // [B, 4] int32
    float4* out4 = (float4*)d_out;                  // [2, B, H] fp32

    dim3 grid(NCHUNKS, B_, 2);
    entity_accum_kernel<<<grid, H4_>>>(seq4, pos, out4);
}